// round 2
// baseline (speedup 1.0000x reference)
#include <cuda_runtime.h>
#include <cstdint>

#define C_IN        128
#define C_OUT       256
#define MAX_LEN     4096
#define PATCH       64
#define PK          9
#define OK          9
#define PAD         4
#define NUM_PATCHES 64
#define BATCH       32

// 64 MiB scratch for stage-1 output (allocation-free rule: __device__ global)
__device__ float g_sa[(size_t)BATCH * C_IN * MAX_LEN];

typedef unsigned long long u64;

__device__ __forceinline__ u64 pk2(float lo, float hi) {
    u64 r;
    asm("mov.b64 %0, {%1,%2};" : "=l"(r) : "f"(lo), "f"(hi));
    return r;
}
__device__ __forceinline__ void unpk2(u64 v, float& lo, float& hi) {
    asm("mov.b64 {%0,%1}, %2;" : "=f"(lo), "=f"(hi) : "l"(v));
}
// Blackwell packed fp32x2 FMA: d = a*b + d (PTX-only path, 2x FFMA rate)
__device__ __forceinline__ void fma2(u64& d, u64 a, u64 b) {
    asm("fma.rn.f32x2 %0, %1, %2, %0;" : "+l"(d) : "l"(a), "l"(b));
}

__device__ __forceinline__ float selu1(float x) {
    const float sc = 1.0507009873554805f;
    const float scal = 1.7580993408473766f;  // sc * alpha
    return x > 0.0f ? sc * x : scal * expm1f(x);
}

// ---------------------------------------------------------------------------
// Stage 1: per-patch depthwise 9-tap conv (zero-padded at patch boundaries).
// PSTRIDE == PATCH, so patches are a pure reshape of x.
// One block per (b, c) row of length 4096.
// ---------------------------------------------------------------------------
__global__ void __launch_bounds__(256) stage1_kernel(const float* __restrict__ x,
                                                     const float* __restrict__ pf) {
    const int row = blockIdx.x;           // b*C_IN + c
    const int c = row & (C_IN - 1);

    __shared__ float xs[MAX_LEN];
    __shared__ float wf[NUM_PATCHES * PK];

    const float* xr = x + (size_t)row * MAX_LEN;
    for (int i = threadIdx.x; i < MAX_LEN / 4; i += blockDim.x)
        reinterpret_cast<float4*>(xs)[i] = reinterpret_cast<const float4*>(xr)[i];
    for (int i = threadIdx.x; i < NUM_PATCHES * PK; i += blockDim.x)
        wf[i] = pf[(size_t)c * (NUM_PATCHES * PK) + i];
    __syncthreads();

    float* orow = g_sa + (size_t)row * MAX_LEN;
    for (int l = threadIdx.x; l < MAX_LEN; l += blockDim.x) {
        const int p = l >> 6;
        const int u = l & 63;
        const float* xp = xs + (p << 6);
        const float* wp = wf + p * PK;
        float s = 0.0f;
#pragma unroll
        for (int k = 0; k < PK; ++k) {
            int j = u + k - PAD;
            if ((unsigned)j < (unsigned)PATCH) s += xp[j] * wp[k];
        }
        orow[l] = s;
    }
}

// ---------------------------------------------------------------------------
// Stage 2: dense conv1d (implicit GEMM, M=256 x K=1152 x N=32*4096) + SELU.
// Block tile: 64 outputs x 256 positions; 256 threads; thread tile 8o x 8l
// held as 32 f32x2 accumulators. Weights staged in smem pre-duplicated as
// float2 so LDS.64 broadcast yields the packed multiplier directly.
// ---------------------------------------------------------------------------
#define BLK_O   64
#define BLK_L   256
#define CC      8              // channels per smem chunk
#define SA_W    (BLK_L + 8)    // 264 floats per staged sa row

__global__ void __launch_bounds__(256) stage2_kernel(const float* __restrict__ W,
                                                     float* __restrict__ out) {
    __shared__ float  sa_s[CC][SA_W];            // 8.25 KB
    __shared__ float2 W_s[BLK_O][CC * OK];       // 36 KB (duplicated weights)

    const int b  = blockIdx.z;
    const int o0 = blockIdx.y * BLK_O;
    const int l0 = blockIdx.x * BLK_L;
    const int tid = threadIdx.x;
    const int tx = tid & 31;       // 32 l-groups, 8 positions each
    const int ty = tid >> 5;       // 8 o-groups, 8 outputs each

    u64 acc[8][4];
#pragma unroll
    for (int oo = 0; oo < 8; ++oo)
#pragma unroll
        for (int p = 0; p < 4; ++p) acc[oo][p] = 0ULL;

    const float* saB = g_sa + (size_t)b * C_IN * MAX_LEN;

    for (int ch0 = 0; ch0 < C_IN; ch0 += CC) {
        __syncthreads();   // protect previous chunk's smem from overwrite

        // stage sa rows (with 4-left/4-right halo, zero at sequence ends)
#pragma unroll
        for (int cc = 0; cc < CC; ++cc) {
            const float* sr = saB + (size_t)(ch0 + cc) * MAX_LEN;
            for (int i = tid; i < SA_W; i += 256) {
                int l = l0 + i - PAD;
                sa_s[cc][i] = ((unsigned)l < (unsigned)MAX_LEN) ? sr[l] : 0.0f;
            }
        }
        // stage weights, duplicated into both float2 lanes
        for (int idx = tid; idx < BLK_O * CC * OK; idx += 256) {
            int o = idx / (CC * OK);
            int j = idx % (CC * OK);
            float w = W[(size_t)(o0 + o) * (C_IN * OK) + (size_t)ch0 * OK + j];
            W_s[o][j] = make_float2(w, w);
        }
        __syncthreads();

#pragma unroll
        for (int cc = 0; cc < CC; ++cc) {
            // 16 consecutive sa values for this thread's 8 positions + 9-tap span
            const float* vr = &sa_s[cc][tx * 8];
            float4 a0 = *reinterpret_cast<const float4*>(vr);
            float4 a1 = *reinterpret_cast<const float4*>(vr + 4);
            float4 a2 = *reinterpret_cast<const float4*>(vr + 8);
            float4 a3 = *reinterpret_cast<const float4*>(vr + 12);
            float v[16] = {a0.x, a0.y, a0.z, a0.w, a1.x, a1.y, a1.z, a1.w,
                           a2.x, a2.y, a2.z, a2.w, a3.x, a3.y, a3.z, a3.w};
            u64 ve[8], vo[7];
#pragma unroll
            for (int q = 0; q < 8; ++q) ve[q] = pk2(v[2 * q], v[2 * q + 1]);
#pragma unroll
            for (int q = 0; q < 7; ++q) vo[q] = pk2(v[2 * q + 1], v[2 * q + 2]);

#pragma unroll
            for (int k = 0; k < OK; ++k) {
                // pairs (v[k+2p], v[k+2p+1]) for p=0..3
                u64 vp0, vp1, vp2, vp3;
                if ((k & 1) == 0) {
                    vp0 = ve[(k >> 1) + 0]; vp1 = ve[(k >> 1) + 1];
                    vp2 = ve[(k >> 1) + 2]; vp3 = ve[(k >> 1) + 3];
                } else {
                    vp0 = vo[(k >> 1) + 0]; vp1 = vo[(k >> 1) + 1];
                    vp2 = vo[(k >> 1) + 2]; vp3 = vo[(k >> 1) + 3];
                }
#pragma unroll
                for (int oo = 0; oo < 8; ++oo) {
                    u64 w2 = *reinterpret_cast<const u64*>(&W_s[ty * 8 + oo][cc * OK + k]);
                    fma2(acc[oo][0], vp0, w2);
                    fma2(acc[oo][1], vp1, w2);
                    fma2(acc[oo][2], vp2, w2);
                    fma2(acc[oo][3], vp3, w2);
                }
            }
        }
    }

    // epilogue: SELU + store (float2 per pair)
#pragma unroll
    for (int oo = 0; oo < 8; ++oo) {
        float* orow = out + ((size_t)b * C_OUT + o0 + ty * 8 + oo) * MAX_LEN + l0 + tx * 8;
#pragma unroll
        for (int p = 0; p < 4; ++p) {
            float lo, hi;
            unpk2(acc[oo][p], lo, hi);
            float2 r = make_float2(selu1(lo), selu1(hi));
            *reinterpret_cast<float2*>(orow + 2 * p) = r;
        }
    }
}

// ---------------------------------------------------------------------------
extern "C" void kernel_launch(void* const* d_in, const int* in_sizes, int n_in,
                              void* d_out, int out_size) {
    const float* x = nullptr;
    const float* pf = nullptr;
    const float* of = nullptr;
    for (int i = 0; i < n_in; ++i) {
        if (in_sizes[i] == BATCH * C_IN * MAX_LEN)            x  = (const float*)d_in[i];
        else if (in_sizes[i] == C_IN * NUM_PATCHES * PK)      pf = (const float*)d_in[i];
        else if (in_sizes[i] == C_OUT * C_IN * OK)            of = (const float*)d_in[i];
    }

    stage1_kernel<<<BATCH * C_IN, 256>>>(x, pf);
    stage2_kernel<<<dim3(MAX_LEN / BLK_L, C_OUT / BLK_O, BATCH), 256>>>(of, (float*)d_out);
}

// round 4
// speedup vs baseline: 4.0567x; 4.0567x over previous
#include <cuda_runtime.h>
#include <cuda_bf16.h>
#include <cstdint>

#define C_IN        128
#define C_OUT       256
#define MAX_LEN     4096
#define PATCH       64
#define PK          9
#define OK          9
#define PAD         4
#define NUM_PATCHES 64
#define BATCH       32

typedef unsigned long long u64;
typedef unsigned int u32;

// ---------------- device scratch (allocation-free rule) ----------------
// stage-1 output, [b][l][c] bf16 hi/lo split
__device__ __nv_bfloat16 g_sat_hi[(size_t)BATCH * MAX_LEN * C_IN];
__device__ __nv_bfloat16 g_sat_lo[(size_t)BATCH * MAX_LEN * C_IN];
// weights repacked [k][c][o] bf16 hi/lo
__device__ __nv_bfloat16 g_w_hi[OK * C_IN * C_OUT];
__device__ __nv_bfloat16 g_w_lo[OK * C_IN * C_OUT];

// ---------------- helpers ----------------
__device__ __forceinline__ u32 smem_u32(const void* p) {
    u32 a;
    asm("{ .reg .u64 t; cvta.to.shared.u64 t, %1; cvt.u32.u64 %0, t; }" : "=r"(a) : "l"(p));
    return a;
}
__device__ __forceinline__ void cp16(u32 dst, const void* src) {
    asm volatile("cp.async.cg.shared.global [%0], [%1], 16;" :: "r"(dst), "l"(src));
}
#define CP_COMMIT() asm volatile("cp.async.commit_group;" ::: "memory")
#define CP_WAIT(N)  asm volatile("cp.async.wait_group %0;" :: "n"(N) : "memory")

__device__ __forceinline__ void ldsm4(u32* r, u32 addr) {
    asm volatile("ldmatrix.sync.aligned.m8n8.x4.shared.b16 {%0,%1,%2,%3}, [%4];"
                 : "=r"(r[0]), "=r"(r[1]), "=r"(r[2]), "=r"(r[3]) : "r"(addr));
}
__device__ __forceinline__ void ldsm4t(u32* r, u32 addr) {
    asm volatile("ldmatrix.sync.aligned.m8n8.x4.trans.shared.b16 {%0,%1,%2,%3}, [%4];"
                 : "=r"(r[0]), "=r"(r[1]), "=r"(r[2]), "=r"(r[3]) : "r"(addr));
}
__device__ __forceinline__ void hmma(float* d, const u32* a, const u32* b) {
    asm volatile("mma.sync.aligned.m16n8k16.row.col.f32.bf16.bf16.f32 "
                 "{%0,%1,%2,%3}, {%4,%5,%6,%7}, {%8,%9}, {%0,%1,%2,%3};"
                 : "+f"(d[0]), "+f"(d[1]), "+f"(d[2]), "+f"(d[3])
                 : "r"(a[0]), "r"(a[1]), "r"(a[2]), "r"(a[3]), "r"(b[0]), "r"(b[1]));
}
__device__ __forceinline__ float selu1(float x) {
    return x > 0.0f ? 1.0507009873554805f * x : 1.7580993408473766f * expm1f(x);
}

// ---------------------------------------------------------------------------
// Weight repack: fp32 W[o][c][k] -> bf16 hi/lo, layout [k][c][o]
// ---------------------------------------------------------------------------
__global__ void wconv_kernel(const float* __restrict__ W) {
    int idx = blockIdx.x * blockDim.x + threadIdx.x;
    if (idx >= OK * C_IN * C_OUT) return;
    int o = idx & 255;
    int c = (idx >> 8) & 127;
    int k = idx >> 15;
    float w = W[((size_t)o * C_IN + c) * OK + k];
    __nv_bfloat16 hi = __float2bfloat16_rn(w);
    __nv_bfloat16 lo = __float2bfloat16_rn(w - __bfloat162float(hi));
    g_w_hi[idx] = hi;
    g_w_lo[idx] = lo;
}

// ---------------------------------------------------------------------------
// Stage 1: per-patch depthwise 9-tap conv (zero pad at patch boundaries),
// output [b][l][c] bf16 hi/lo (c contiguous -> coalesced across threads).
// ---------------------------------------------------------------------------
__global__ void __launch_bounds__(256) stage1_kernel(const float* __restrict__ x,
                                                     const float* __restrict__ pf) {
    const int b = blockIdx.y;
    const int P = blockIdx.x;
    const int p0 = P * PATCH;

    __shared__ float xs[C_IN][65];
    __shared__ float wf[C_IN * PK];

    for (int idx = threadIdx.x; idx < C_IN * PATCH; idx += 256) {
        int c = idx >> 6, u = idx & 63;
        xs[c][u] = x[((size_t)b * C_IN + c) * MAX_LEN + p0 + u];
    }
    for (int idx = threadIdx.x; idx < C_IN * PK; idx += 256) {
        int c = idx / PK, kk = idx % PK;
        wf[idx] = pf[((size_t)c * NUM_PATCHES + P) * PK + kk];
    }
    __syncthreads();

    const int c  = threadIdx.x & 127;
    const int ug = threadIdx.x >> 7;
    const float* wr = &wf[c * PK];
#pragma unroll
    for (int i = 0; i < 32; ++i) {
        int u = ug * 32 + i;
        float s = 0.0f;
#pragma unroll
        for (int k = 0; k < PK; ++k) {
            int j = u + k - PAD;
            if ((unsigned)j < (unsigned)PATCH) s += xs[c][j] * wr[k];
        }
        __nv_bfloat16 hi = __float2bfloat16_rn(s);
        __nv_bfloat16 lo = __float2bfloat16_rn(s - __bfloat162float(hi));
        size_t off = ((size_t)b * MAX_LEN + p0 + u) * C_IN + c;
        g_sat_hi[off] = hi;
        g_sat_lo[off] = lo;
    }
}

// ---------------------------------------------------------------------------
// Stage 2: bf16 split implicit-GEMM conv via mma.sync.m16n8k16 + SELU.
// CTA = 128 positions (M) x 128 outputs (N). 8 warps = 4(l) x 2(o).
// A = sa [l][c] row-major in smem (tap shift = row shift, alignment-safe).
// B = weights [c][o] via ldmatrix.trans, double-buffered cp.async per tap.
// ---------------------------------------------------------------------------
#define BL 128
#define SA_STRIDE 272                       // bytes per l-row (136 halves, padded)
#define SA_ROWS   136                       // BL + 8 halo
#define SA_HALF   (SA_ROWS * SA_STRIDE)     // 36992
#define SA_END    (2 * SA_HALF)             // 73984
#define W_STRIDE  272                       // bytes per c-row (136 halves, padded)
#define W_HALF    (C_IN * W_STRIDE)         // 34816
#define W_BUF     (2 * W_HALF)              // 69632 (hi + lo)
#define SMEM_TOTAL (SA_END + 2 * W_BUF)     // 213248

__global__ void __launch_bounds__(256, 1) stage2_kernel(float* __restrict__ out) {
    extern __shared__ char smem[];
    const u32 sb = smem_u32(smem);
    const int tid  = threadIdx.x;
    const int wid  = tid >> 5;
    const int lane = tid & 31;
    const int wl   = wid & 3;        // warp l-offset: wl*32
    const int wo   = wid >> 2;       // warp o-offset: wo*64
    const int b   = blockIdx.z;
    const int o0  = blockIdx.y * 128;
    const int l0  = blockIdx.x * BL;

    // ---- fill sa tile (hi/lo), rows l0-4 .. l0+131, zero outside sequence ----
    {
        const __nv_bfloat16* sh = g_sat_hi + (size_t)b * MAX_LEN * C_IN;
        const __nv_bfloat16* sl = g_sat_lo + (size_t)b * MAX_LEN * C_IN;
        for (int idx = tid; idx < SA_ROWS * 16; idx += 256) {
            int row = idx >> 4, j = idx & 15;
            int l = l0 - PAD + row;
            uint4 vh = make_uint4(0, 0, 0, 0), vl = vh;
            if ((unsigned)l < (unsigned)MAX_LEN) {
                size_t base = (size_t)l * C_IN + j * 8;
                vh = *reinterpret_cast<const uint4*>(sh + base);
                vl = *reinterpret_cast<const uint4*>(sl + base);
            }
            *reinterpret_cast<uint4*>(smem + row * SA_STRIDE + j * 16) = vh;
            *reinterpret_cast<uint4*>(smem + SA_HALF + row * SA_STRIDE + j * 16) = vl;
        }
    }

    // ---- weight copy helper: tap t -> buffer buf ----
    auto copy_w = [&](int t, int buf) {
        const u32 dst0 = sb + SA_END + buf * W_BUF;
        for (int idx = tid; idx < 4096; idx += 256) {
            int half = idx >> 11;          // 0 = hi, 1 = lo
            int r = (idx >> 4) & 127;      // c row
            int j = idx & 15;              // 16B chunk within 256B of o
            u32 dst = dst0 + half * W_HALF + r * W_STRIDE + j * 16;
            const __nv_bfloat16* src =
                (half ? g_w_lo : g_w_hi) + ((size_t)t * C_IN + r) * C_OUT + o0 + j * 8;
            cp16(dst, src);
        }
        CP_COMMIT();
    };

    float acc[2][8][4];
#pragma unroll
    for (int mt = 0; mt < 2; ++mt)
#pragma unroll
        for (int nt = 0; nt < 8; ++nt)
#pragma unroll
            for (int e = 0; e < 4; ++e) acc[mt][nt][e] = 0.0f;

    copy_w(0, 0);

    const int lrow = lane & 15;
    const int lcol = lane >> 4;

    for (int k = 0; k < OK; ++k) {
        const int buf = k & 1;
        if (k < OK - 1) {
            copy_w(k + 1, buf ^ 1);
            CP_WAIT(1);
        } else {
            CP_WAIT(0);
        }
        __syncthreads();    // weights for tap k visible; sa visible (k==0)

        const u32 whi = sb + SA_END + buf * W_BUF;
        const u32 wlo = whi + W_HALF;

#pragma unroll
        for (int chunk = 0; chunk < 8; ++chunk) {
            // A frags (sa): 2 m16 tiles, hi & lo
            u32 a_hi[2][4], a_lo[2][4];
#pragma unroll
            for (int mt = 0; mt < 2; ++mt) {
                int row = wl * 32 + mt * 16 + k + lrow;
                u32 addr = sb + row * SA_STRIDE + chunk * 32 + lcol * 16;
                ldsm4(a_hi[mt], addr);
                ldsm4(a_lo[mt], addr + SA_HALF);
            }
            // B frags (weights): 8 n8 tiles via 4 x4.trans, hi & lo
            u32 b_hi[8][2], b_lo[8][2];
#pragma unroll
            for (int g = 0; g < 4; ++g) {
                u32 off = (u32)(chunk * 16 + lrow) * W_STRIDE +
                          2u * (wo * 64 + g * 16) + lcol * 16;
                u32 r[4];
                ldsm4t(r, whi + off);
                b_hi[2 * g][0] = r[0]; b_hi[2 * g][1] = r[1];
                b_hi[2 * g + 1][0] = r[2]; b_hi[2 * g + 1][1] = r[3];
                ldsm4t(r, wlo + off);
                b_lo[2 * g][0] = r[0]; b_lo[2 * g][1] = r[1];
                b_lo[2 * g + 1][0] = r[2]; b_lo[2 * g + 1][1] = r[3];
            }
            // 3-term split MMAs
#pragma unroll
            for (int mt = 0; mt < 2; ++mt)
#pragma unroll
                for (int nt = 0; nt < 8; ++nt) {
                    hmma(acc[mt][nt], a_hi[mt], b_hi[nt]);
                    hmma(acc[mt][nt], a_hi[mt], b_lo[nt]);
                    hmma(acc[mt][nt], a_lo[mt], b_hi[nt]);
                }
        }
        __syncthreads();    // tap k compute done before buf is overwritten
    }

    // ---- epilogue: SELU -> smem transpose [o][132 l] -> coalesced STG ----
    float* epi = reinterpret_cast<float*>(smem);
#pragma unroll
    for (int mt = 0; mt < 2; ++mt)
#pragma unroll
        for (int nt = 0; nt < 8; ++nt)
#pragma unroll
            for (int e = 0; e < 4; ++e) {
                int l_l = wl * 32 + mt * 16 + (lane >> 2) + ((e >= 2) ? 8 : 0);
                int o_l = wo * 64 + nt * 8 + (lane & 3) * 2 + (e & 1);
                epi[o_l * 132 + l_l] = selu1(acc[mt][nt][e]);
            }
    __syncthreads();
    {
        const int o = tid >> 1;
        const int lh = tid & 1;
        const float4* src = reinterpret_cast<const float4*>(epi + o * 132 + lh * 64);
        float4* dst = reinterpret_cast<float4*>(
            out + ((size_t)b * C_OUT + o0 + o) * MAX_LEN + l0 + lh * 64);
#pragma unroll
        for (int j = 0; j < 16; ++j) dst[j] = src[j];
    }
}

// ---------------------------------------------------------------------------
extern "C" void kernel_launch(void* const* d_in, const int* in_sizes, int n_in,
                              void* d_out, int out_size) {
    const float* x = nullptr;
    const float* pf = nullptr;
    const float* of = nullptr;
    for (int i = 0; i < n_in; ++i) {
        if (in_sizes[i] == BATCH * C_IN * MAX_LEN)       x  = (const float*)d_in[i];
        else if (in_sizes[i] == C_IN * NUM_PATCHES * PK) pf = (const float*)d_in[i];
        else if (in_sizes[i] == C_OUT * C_IN * OK)       of = (const float*)d_in[i];
    }

    static bool attr_set = false;
    if (!attr_set) {
        cudaFuncSetAttribute(stage2_kernel,
                             cudaFuncAttributeMaxDynamicSharedMemorySize, SMEM_TOTAL);
        attr_set = true;
    }

    wconv_kernel<<<(OK * C_IN * C_OUT + 255) / 256, 256>>>(of);
    stage1_kernel<<<dim3(NUM_PATCHES, BATCH), 256>>>(x, pf);
    stage2_kernel<<<dim3(MAX_LEN / BL, C_OUT / 128, BATCH), 256, SMEM_TOTAL>>>((float*)d_out);
}